// round 4
// baseline (speedup 1.0000x reference)
#include <cuda_runtime.h>

#define NN 50000
#define NE 640000
#define DD 128

// ---------------- scratch (device globals: allocation-free) ----------------
__device__ float    g_dinv[NN];        // deg accumulator -> deg^-0.5
__device__ float    g_h[NN * DD];      // x @ W
__device__ float    g_z[NN * DD];      // GCN output (z)
__device__ float    g_E[NN];           // per-node Dirichlet energy
__device__ float    g_coef[NN];        // 2 * weight * lambda
__device__ unsigned g_umax;            // ordered-key max of u = -E/T
__device__ float    g_sumexp;
__device__ float    g_H;
__device__ float    g_logZ;
__device__ int      g_is64;            // edge_index dtype flag

// ---------------- helpers ----------------
__device__ __forceinline__ unsigned f2key(float f) {
    unsigned b = __float_as_uint(f);
    return b ^ ((b >> 31) ? 0xFFFFFFFFu : 0x80000000u);
}
__device__ __forceinline__ float key2f(unsigned k) {
    unsigned b = (k >> 31) ? (k ^ 0x80000000u) : ~k;
    return __uint_as_float(b);
}
__device__ __forceinline__ void red_add_v4(float* p, float a, float b, float c, float d) {
    asm volatile("red.global.add.v4.f32 [%0], {%1,%2,%3,%4};"
                 :: "l"(p), "f"(a), "f"(b), "f"(c), "f"(d) : "memory");
}
__device__ __forceinline__ float warp_sum(float v) {
#pragma unroll
    for (int o = 16; o; o >>= 1) v += __shfl_xor_sync(0xffffffffu, v, o);
    return v;
}
__device__ __forceinline__ unsigned warp_max(unsigned v) {
#pragma unroll
    for (int o = 16; o; o >>= 1) {
        unsigned w = __shfl_xor_sync(0xffffffffu, v, o);
        v = (w > v) ? w : v;
    }
    return v;
}
__device__ __forceinline__ int2 get_edge(const void* ei, int e, int is64) {
    int2 r;
    if (is64) {
        const long long* p = (const long long*)ei;
        r.x = (int)p[e];
        r.y = (int)p[NE + e];
    } else {
        const int* p = (const int*)ei;
        r.x = p[e];
        r.y = p[NE + e];
    }
    return r;
}

// ---------------- kernels ----------------

// Sniff edge_index dtype: int64 little-endian => every odd 32-bit word is 0
// (indices < 50000). 512 consecutive odd-word zeros is impossible for int32 data.
__global__ void k_detect(const int* ei) {
    __shared__ int ok;
    if (threadIdx.x == 0) ok = 1;
    __syncthreads();
    for (int i = threadIdx.x; i < 512; i += blockDim.x) {
        int hi = ei[2 * i + 1];
        unsigned lo = (unsigned)ei[2 * i];
        if (hi != 0 || lo >= NN) ok = 0;
    }
    __syncthreads();
    if (threadIdx.x == 0) g_is64 = ok;
}

__global__ void k_init() {
    int i = blockIdx.x * blockDim.x + threadIdx.x;
    if (i < NN) {
        g_dinv[i] = 1.0f;   // self-loop
        g_E[i]    = 0.0f;
    }
    if (i == 0) {
        g_umax   = 0u;      // below key(-inf): identity for max
        g_sumexp = 0.0f;
        g_H      = 0.0f;
    }
}

__global__ void k_deg(const void* ei) {
    int e = blockIdx.x * blockDim.x + threadIdx.x;
    if (e >= NE) return;
    int is64 = g_is64;
    int d = is64 ? (int)((const long long*)ei)[NE + e] : ((const int*)ei)[NE + e];
    atomicAdd(&g_dinv[d], 1.0f);
}

__global__ void k_dinv() {
    int i = blockIdx.x * blockDim.x + threadIdx.x;
    if (i < NN) g_dinv[i] = rsqrtf(g_dinv[i]);
}

// h = x @ W  (fp32; 64-row tile in smem, W float4 via L1)
__global__ void __launch_bounds__(256) k_gemm(const float* __restrict__ x,
                                              const float* __restrict__ W) {
    __shared__ float xs[64 * DD];
    int row0 = blockIdx.x * 64;
    float4* xs4 = (float4*)xs;
    const float4* x4 = (const float4*)x;
    for (int i = threadIdx.x; i < 64 * 32; i += 256) {
        int r = row0 + (i >> 5);
        xs4[i] = (r < NN) ? x4[r * 32 + (i & 31)] : make_float4(0.f, 0.f, 0.f, 0.f);
    }
    __syncthreads();

    int cg = threadIdx.x & 31;   // 4 output cols: 4*cg..4*cg+3
    int rg = threadIdx.x >> 5;   // 8 rows each
    const float4* W4 = (const float4*)W;
    float4 acc[8];
#pragma unroll
    for (int i = 0; i < 8; i++) acc[i] = make_float4(0.f, 0.f, 0.f, 0.f);

    const float* xrow = xs + (rg * 8) * DD;
#pragma unroll 8
    for (int k = 0; k < DD; k++) {
        float4 w = __ldg(&W4[k * 32 + cg]);
#pragma unroll
        for (int i = 0; i < 8; i++) {
            float xv = xrow[i * DD + k];
            acc[i].x += xv * w.x;
            acc[i].y += xv * w.y;
            acc[i].z += xv * w.z;
            acc[i].w += xv * w.w;
        }
    }
    float4* h4 = (float4*)g_h;
#pragma unroll
    for (int i = 0; i < 8; i++) {
        int r = row0 + rg * 8 + i;
        if (r < NN) h4[r * 32 + cg] = acc[i];
    }
}

// z = b + dinv[n]^2 * h[n]   (self-loop term + bias)
__global__ void k_selfloop(const float* __restrict__ b) {
    int t = blockIdx.x * blockDim.x + threadIdx.x;
    if (t >= NN * 32) return;
    int n = t >> 5, j = t & 31;
    float4 hv = ((const float4*)g_h)[t];
    float4 bb = __ldg(&((const float4*)b)[j]);
    float s = g_dinv[n];
    float s2 = s * s;
    float4 z;
    z.x = bb.x + s2 * hv.x;
    z.y = bb.y + s2 * hv.y;
    z.z = bb.z + s2 * hv.z;
    z.w = bb.w + s2 * hv.w;
    ((float4*)g_z)[t] = z;
}

// GCN message scatter: z[d] += dinv[s]*dinv[d] * h[s]   (warp per edge)
__global__ void k_scatter(const void* ei) {
    int t = blockIdx.x * blockDim.x + threadIdx.x;
    int e = t >> 5;
    if (e >= NE) return;
    int lane = t & 31;
    int2 sd = get_edge(ei, e, g_is64);
    float norm = g_dinv[sd.x] * g_dinv[sd.y];
    float4 v = ((const float4*)g_h)[sd.x * 32 + lane];
    red_add_v4(&g_z[sd.y * DD + lane * 4],
               norm * v.x, norm * v.y, norm * v.z, norm * v.w);
}

// E[d] += ||z[s] - z[d]||^2   (warp per edge)
__global__ void k_energy(const void* ei) {
    int t = blockIdx.x * blockDim.x + threadIdx.x;
    int e = t >> 5;
    if (e >= NE) return;
    int lane = t & 31;
    int2 sd = get_edge(ei, e, g_is64);
    float4 a = ((const float4*)g_z)[sd.x * 32 + lane];
    float4 c = ((const float4*)g_z)[sd.y * 32 + lane];
    float dx = a.x - c.x, dy = a.y - c.y, dz = a.z - c.z, dw = a.w - c.w;
    float s = dx * dx + dy * dy + dz * dz + dw * dw;
    s = warp_sum(s);
    if (lane == 0) atomicAdd(&g_E[sd.y], s);
}

__global__ void k_umax(const float* __restrict__ temp) {
    int i = blockIdx.x * blockDim.x + threadIdx.x;
    float T = temp[0];
    unsigned key = 0u;
    if (i < NN) key = f2key(-g_E[i] / T);
    key = warp_max(key);
    if ((threadIdx.x & 31) == 0) atomicMax(&g_umax, key);
}

__global__ void k_sumexp(const float* __restrict__ temp) {
    int i = blockIdx.x * blockDim.x + threadIdx.x;
    float T = temp[0];
    float m = key2f(g_umax);
    float v = 0.f;
    if (i < NN) v = expf(-g_E[i] / T - m);
    v = warp_sum(v);
    if ((threadIdx.x & 31) == 0) atomicAdd(&g_sumexp, v);
}

__global__ void k_logz() {
    if (blockIdx.x == 0 && threadIdx.x == 0)
        g_logZ = key2f(g_umax) + logf(g_sumexp);
}

__global__ void k_entropy(const float* __restrict__ temp) {
    int i = blockIdx.x * blockDim.x + threadIdx.x;
    float T = temp[0];
    float lz = g_logZ;
    float v = 0.f;
    if (i < NN) {
        float lp = -g_E[i] / T - lz;
        float p = expf(lp);
        v = -p * lp;           // p==0 exactly => 0 * finite = 0
    }
    v = warp_sum(v);
    if ((threadIdx.x & 31) == 0) atomicAdd(&g_H, v);
}

// coef[n] = 2 * weight * lambda_n,   lambda_n = p_n (log p_n + H) / T
__global__ void k_coef(const float* __restrict__ temp,
                       const float* __restrict__ weight) {
    int i = blockIdx.x * blockDim.x + threadIdx.x;
    if (i >= NN) return;
    float T = temp[0];
    float lp = -g_E[i] / T - g_logZ;
    float p = expf(lp);
    float lam = p * (lp + g_H) / T;
    g_coef[i] = 2.0f * weight[0] * lam;
}

__global__ void k_copy(float* __restrict__ out) {
    int t = blockIdx.x * blockDim.x + threadIdx.x;
    if (t < NN * 32) ((float4*)out)[t] = ((const float4*)g_z)[t];
}

// gradient scatter: out[s] += c*diff, out[d] -= c*diff, c = coef[d]
// p underflows to exact 0 for nearly all nodes -> most edges are free.
__global__ void k_grad(const void* ei, float* __restrict__ out) {
    int t = blockIdx.x * blockDim.x + threadIdx.x;
    int e = t >> 5;
    if (e >= NE) return;
    int lane = t & 31;
    int2 sd = get_edge(ei, e, g_is64);
    float c = g_coef[sd.y];
    if (c == 0.0f) return;
    float4 a = ((const float4*)g_z)[sd.x * 32 + lane];
    float4 b = ((const float4*)g_z)[sd.y * 32 + lane];
    float dx = a.x - b.x, dy = a.y - b.y, dz = a.z - b.z, dw = a.w - b.w;
    red_add_v4(&out[sd.x * DD + lane * 4],  c * dx,  c * dy,  c * dz,  c * dw);
    red_add_v4(&out[sd.y * DD + lane * 4], -c * dx, -c * dy, -c * dz, -c * dw);
}

// ---------------- launch ----------------
extern "C" void kernel_launch(void* const* d_in, const int* in_sizes, int n_in,
                              void* d_out, int out_size) {
    const float* x      = (const float*)d_in[0];
    const void*  ei     = d_in[1];
    const float* weight = (const float*)d_in[2];
    const float* temp   = (const float*)d_in[3];
    const float* W      = (const float*)d_in[4];
    const float* b      = (const float*)d_in[5];
    float* out = (float*)d_out;

    const int TB = 256;
    const int gN  = (NN + TB - 1) / TB;          // node-wise grids
    const int gE  = (NE + TB - 1) / TB;          // edge-wise (thread per edge)
    const int gEW = (NE * 32) / TB;              // edge-wise (warp per edge) = 80000
    const int gV  = (NN * 32 + TB - 1) / TB;     // feature-wise (float4 lanes)

    k_detect  <<<1, TB>>>((const int*)ei);
    k_init    <<<gN, TB>>>();
    k_deg     <<<gE, TB>>>(ei);
    k_dinv    <<<gN, TB>>>();
    k_gemm    <<<(NN + 63) / 64, TB>>>(x, W);
    k_selfloop<<<gV, TB>>>(b);
    k_scatter <<<gEW, TB>>>(ei);
    k_energy  <<<gEW, TB>>>(ei);
    k_umax    <<<gN, TB>>>(temp);
    k_sumexp  <<<gN, TB>>>(temp);
    k_logz    <<<1, 32>>>();
    k_entropy <<<gN, TB>>>(temp);
    k_coef    <<<gN, TB>>>(temp, weight);
    k_copy    <<<gV, TB>>>(out);
    k_grad    <<<gEW, TB>>>(ei, out);
}

// round 5
// speedup vs baseline: 1.0809x; 1.0809x over previous
#include <cuda_runtime.h>

#define NN 50000
#define NE 640000
#define DD 128

// ---------------- scratch (device globals: allocation-free) ----------------
struct Scr {               // zeroed by one cudaMemsetAsync each call
    float    deg[NN];      // degree accumulator (later holds nothing; dinv separate)
    float    E[NN];        // per-node Dirichlet energy
    float    S;            // sum exp(u - m)
    float    U;            // sum exp(u - m) * u
    unsigned umax;         // ordered-key max of u = -E/T   (0 is below all keys)
    int      qn;           // active-edge queue count
};
__device__ Scr   g_s;
__device__ float g_dinv[NN];
__device__ float g_h[NN * DD];     // x @ W
__device__ float g_z[NN * DD];     // GCN output
__device__ int   g_src[NE];        // int32 edge copies
__device__ int   g_dst[NE];
__device__ int   g_q[NE];          // active edge queue

// ---------------- helpers ----------------
__device__ __forceinline__ unsigned f2key(float f) {
    unsigned b = __float_as_uint(f);
    return b ^ ((b >> 31) ? 0xFFFFFFFFu : 0x80000000u);
}
__device__ __forceinline__ float key2f(unsigned k) {
    unsigned b = (k >> 31) ? (k ^ 0x80000000u) : ~k;
    return __uint_as_float(b);
}
__device__ __forceinline__ void red_add_v4(float* p, float a, float b, float c, float d) {
    asm volatile("red.global.add.v4.f32 [%0], {%1,%2,%3,%4};"
                 :: "l"(p), "f"(a), "f"(b), "f"(c), "f"(d) : "memory");
}
__device__ __forceinline__ float warp_sum(float v) {
#pragma unroll
    for (int o = 16; o; o >>= 1) v += __shfl_xor_sync(0xffffffffu, v, o);
    return v;
}
__device__ __forceinline__ unsigned warp_max(unsigned v) {
#pragma unroll
    for (int o = 16; o; o >>= 1) {
        unsigned w = __shfl_xor_sync(0xffffffffu, v, o);
        v = (w > v) ? w : v;
    }
    return v;
}
// coef[n] = 2*weight*lambda_n, lambda = p(log p + H)/T,
// H = lz - U/S, lz = m + log S. Exact 0 when p underflows.
__device__ __forceinline__ float coef_of(float En, float T, float m,
                                         float S, float U, float w2) {
    float lz = m + logf(S);
    float H  = lz - U / S;          // lz = m+logS; U/S = E[u]; H = lz - E[u]
    float lp = -En / T - lz;
    float p  = expf(lp);
    return w2 * (p * (lp + H) / T);
}

// ---------------- kernels ----------------

// Per-block int64/int32 sniff + convert edges to int32 + degree count.
// int64 little-endian with idx<50000 => odd 32-bit words of first 128 pairs all 0.
__global__ void k_prep(const void* ei) {
    __shared__ int s_is64;
    int tid = threadIdx.x;
    if (tid == 0) s_is64 = 1;
    __syncthreads();
    const int* w = (const int*)ei;
    if (tid < 128) {
        int hi = w[2 * tid + 1];
        unsigned lo = (unsigned)w[2 * tid];
        if (hi != 0 || lo >= NN) s_is64 = 0;   // benign race
    }
    __syncthreads();
    int is64 = s_is64;
    int e = blockIdx.x * blockDim.x + tid;
    if (e >= NE) return;
    int s, d;
    if (is64) {
        s = (int)((const long long*)ei)[e];
        d = (int)((const long long*)ei)[NE + e];
    } else {
        s = w[e];
        d = w[NE + e];
    }
    g_src[e] = s;
    g_dst[e] = d;
    atomicAdd(&g_s.deg[d], 1.0f);
}

// h = x @ W  (fp32; 64-row tile in smem, W float4 via L1)
__global__ void __launch_bounds__(256) k_gemm(const float* __restrict__ x,
                                              const float* __restrict__ W) {
    __shared__ float xs[64 * DD];
    int row0 = blockIdx.x * 64;
    float4* xs4 = (float4*)xs;
    const float4* x4 = (const float4*)x;
    for (int i = threadIdx.x; i < 64 * 32; i += 256) {
        int r = row0 + (i >> 5);
        xs4[i] = (r < NN) ? x4[r * 32 + (i & 31)] : make_float4(0.f, 0.f, 0.f, 0.f);
    }
    __syncthreads();

    int cg = threadIdx.x & 31;
    int rg = threadIdx.x >> 5;
    const float4* W4 = (const float4*)W;
    float4 acc[8];
#pragma unroll
    for (int i = 0; i < 8; i++) acc[i] = make_float4(0.f, 0.f, 0.f, 0.f);

    const float* xrow = xs + (rg * 8) * DD;
#pragma unroll 8
    for (int k = 0; k < DD; k++) {
        float4 w = __ldg(&W4[k * 32 + cg]);
#pragma unroll
        for (int i = 0; i < 8; i++) {
            float xv = xrow[i * DD + k];
            acc[i].x += xv * w.x;
            acc[i].y += xv * w.y;
            acc[i].z += xv * w.z;
            acc[i].w += xv * w.w;
        }
    }
    float4* h4 = (float4*)g_h;
#pragma unroll
    for (int i = 0; i < 8; i++) {
        int r = row0 + rg * 8 + i;
        if (r < NN) h4[r * 32 + cg] = acc[i];
    }
}

// dinv = rsqrt(deg+1);  z = b + dinv^2 * h   (warp per node)
__global__ void k_selfloop(const float* __restrict__ b) {
    int t = blockIdx.x * blockDim.x + threadIdx.x;
    if (t >= NN * 32) return;
    int n = t >> 5, j = t & 31;
    float s = rsqrtf(g_s.deg[n] + 1.0f);   // +1 = self-loop
    if (j == 0) g_dinv[n] = s;
    float s2 = s * s;
    float4 hv = ((const float4*)g_h)[t];
    float4 bb = __ldg(&((const float4*)b)[j]);
    float4 z;
    z.x = bb.x + s2 * hv.x;
    z.y = bb.y + s2 * hv.y;
    z.z = bb.z + s2 * hv.z;
    z.w = bb.w + s2 * hv.w;
    ((float4*)g_z)[t] = z;
}

// z[d] += dinv[s]*dinv[d] * h[s]   (warp per edge)
__global__ void k_scatter() {
    int t = blockIdx.x * blockDim.x + threadIdx.x;
    int e = t >> 5;
    if (e >= NE) return;
    int lane = t & 31;
    int s = g_src[e], d = g_dst[e];
    float norm = g_dinv[s] * g_dinv[d];
    float4 v = ((const float4*)g_h)[s * 32 + lane];
    red_add_v4(&g_z[d * DD + lane * 4],
               norm * v.x, norm * v.y, norm * v.z, norm * v.w);
}

// E[d] += ||z[s] - z[d]||^2   (warp per edge)
__global__ void k_energy() {
    int t = blockIdx.x * blockDim.x + threadIdx.x;
    int e = t >> 5;
    if (e >= NE) return;
    int lane = t & 31;
    int s = g_src[e], d = g_dst[e];
    float4 a = __ldg(&((const float4*)g_z)[s * 32 + lane]);
    float4 c = __ldg(&((const float4*)g_z)[d * 32 + lane]);
    float dx = a.x - c.x, dy = a.y - c.y, dz = a.z - c.z, dw = a.w - c.w;
    float v = dx * dx + dy * dy + dz * dz + dw * dw;
    v = warp_sum(v);
    if (lane == 0) atomicAdd(&g_s.E[d], v);
}

__global__ void k_umax(const float* __restrict__ temp) {
    int i = blockIdx.x * blockDim.x + threadIdx.x;
    float T = temp[0];
    unsigned key = 0u;
    if (i < NN) key = f2key(-g_s.E[i] / T);
    key = warp_max(key);
    if ((threadIdx.x & 31) == 0) atomicMax(&g_s.umax, key);
}

// Fused: S = sum e^{u-m}, U = sum e^{u-m}*u   AND   out = z (copy).
// Warp per node: lanes copy, lane0 computes exp terms; one atomic pair per block.
__global__ void __launch_bounds__(256) k_sumcopy(const float* __restrict__ temp,
                                                 float* __restrict__ out) {
    __shared__ float sS[8], sU[8];
    int t = blockIdx.x * blockDim.x + threadIdx.x;
    int wip = threadIdx.x >> 5;   // warp in block
    int lane = threadIdx.x & 31;
    float vS = 0.f, vU = 0.f;
    if (t < NN * 32) {
        int n = t >> 5;
        ((float4*)out)[t] = ((const float4*)g_z)[t];
        if (lane == 0) {
            float T = temp[0];
            float m = key2f(g_s.umax);
            float u = -g_s.E[n] / T;
            float ex = expf(u - m);
            vS = ex;
            vU = ex * u;
        }
    }
    if (lane == 0) { sS[wip] = vS; sU[wip] = vU; }
    __syncthreads();
    if (threadIdx.x == 0) {
        float aS = 0.f, aU = 0.f;
#pragma unroll
        for (int i = 0; i < 8; i++) { aS += sS[i]; aU += sU[i]; }
        atomicAdd(&g_s.S, aS);
        atomicAdd(&g_s.U, aU);
    }
}

// Build active-edge queue: thread per edge; coef recomputed from E[dst].
__global__ void k_qbuild(const float* __restrict__ temp,
                         const float* __restrict__ weight) {
    int e = blockIdx.x * blockDim.x + threadIdx.x;
    if (e >= NE) return;
    float T = temp[0];
    float m = key2f(g_s.umax);
    float c = coef_of(g_s.E[g_dst[e]], T, m, g_s.S, g_s.U, 2.0f * weight[0]);
    if (c != 0.0f) {
        int i = atomicAdd(&g_s.qn, 1);
        g_q[i] = e;
    }
}

// Process queue (persistent warps): out[s] += c*diff, out[d] -= c*diff.
__global__ void k_gradq(const float* __restrict__ temp,
                        const float* __restrict__ weight,
                        float* __restrict__ out) {
    int gw = (blockIdx.x * blockDim.x + threadIdx.x) >> 5;
    int nw = (gridDim.x * blockDim.x) >> 5;
    int lane = threadIdx.x & 31;
    int qn = g_s.qn;
    float T = temp[0];
    float m = key2f(g_s.umax);
    float w2 = 2.0f * weight[0];
    float S = g_s.S, U = g_s.U;
    for (int i = gw; i < qn; i += nw) {
        int e = g_q[i];
        int s = g_src[e], d = g_dst[e];
        float c = coef_of(g_s.E[d], T, m, S, U, w2);
        float4 a = ((const float4*)g_z)[s * 32 + lane];
        float4 b = ((const float4*)g_z)[d * 32 + lane];
        float dx = a.x - b.x, dy = a.y - b.y, dz = a.z - b.z, dw = a.w - b.w;
        red_add_v4(&out[s * DD + lane * 4],  c * dx,  c * dy,  c * dz,  c * dw);
        red_add_v4(&out[d * DD + lane * 4], -c * dx, -c * dy, -c * dz, -c * dw);
    }
}

// ---------------- launch ----------------
extern "C" void kernel_launch(void* const* d_in, const int* in_sizes, int n_in,
                              void* d_out, int out_size) {
    const float* x      = (const float*)d_in[0];
    const void*  ei     = d_in[1];
    const float* weight = (const float*)d_in[2];
    const float* temp   = (const float*)d_in[3];
    const float* W      = (const float*)d_in[4];
    const float* b      = (const float*)d_in[5];
    float* out = (float*)d_out;

    void* scr = nullptr;
    cudaGetSymbolAddress(&scr, g_s);
    cudaMemsetAsync(scr, 0, sizeof(Scr));   // deg, E, S, U, umax, qn all zero

    const int TB = 256;
    const int gE  = (NE + TB - 1) / TB;         // 2500
    const int gEW = (NE * 32) / TB;             // 80000
    const int gV  = (NN * 32 + TB - 1) / TB;    // 6250
    const int gN  = (NN + TB - 1) / TB;         // 196

    k_prep    <<<gE, TB>>>(ei);
    k_gemm    <<<(NN + 63) / 64, TB>>>(x, W);
    k_selfloop<<<gV, TB>>>(b);
    k_scatter <<<gEW, TB>>>();
    k_energy  <<<gEW, TB>>>();
    k_umax    <<<gN, TB>>>(temp);
    k_sumcopy <<<gV, TB>>>(temp, out);
    k_qbuild  <<<gE, TB>>>(temp, weight);
    k_gradq   <<<232, TB>>>(temp, weight, out);
}

// round 6
// speedup vs baseline: 1.6543x; 1.5304x over previous
#include <cuda_runtime.h>

#define NN 50000
#define NE 640000
#define DD 128
#define NB 196            // ceil(NN/256)

// ---------------- scratch (device globals: allocation-free) ----------------
struct Scr {               // zeroed by one cudaMemsetAsync each call
    int      degi[NN];     // in-degree histogram
    float    E[NN];        // per-node Dirichlet energy
    float    S;            // sum exp(u - m)
    float    U;            // sum exp(u - m) * u
    unsigned umax;         // ordered-key max of u = -E/T (0 below all keys)
    int      qn;           // active-node queue count
};
__device__ Scr   g_s;
__device__ float g_dinv[NN];
__device__ float g_h[NN * DD];     // x @ W
__device__ float g_z[NN * DD];     // GCN output
__device__ int   g_src[NE];        // int32 edge copies
__device__ int   g_dst[NE];
__device__ int   g_rowp[NN + 1];   // CSR row pointer (by dst)
__device__ int   g_cur[NN];        // fill cursors
__device__ int   g_csr[NE];        // src ids grouped by dst
__device__ int   g_bsum[NB];       // scan partials
__device__ int   g_boff[NB];
__device__ int   g_q[NN];          // active node queue

// ---------------- helpers ----------------
__device__ __forceinline__ unsigned f2key(float f) {
    unsigned b = __float_as_uint(f);
    return b ^ ((b >> 31) ? 0xFFFFFFFFu : 0x80000000u);
}
__device__ __forceinline__ float key2f(unsigned k) {
    unsigned b = (k >> 31) ? (k ^ 0x80000000u) : ~k;
    return __uint_as_float(b);
}
__device__ __forceinline__ void red_add_v4(float* p, float a, float b, float c, float d) {
    asm volatile("red.global.add.v4.f32 [%0], {%1,%2,%3,%4};"
                 :: "l"(p), "f"(a), "f"(b), "f"(c), "f"(d) : "memory");
}
__device__ __forceinline__ float warp_sum(float v) {
#pragma unroll
    for (int o = 16; o; o >>= 1) v += __shfl_xor_sync(0xffffffffu, v, o);
    return v;
}
// coef[n] = 2*weight*lambda_n, lambda = p(log p + H)/T; exact 0 when p underflows.
__device__ __forceinline__ float coef_of(float En, float T, float m,
                                         float S, float U, float w2) {
    float lz = m + logf(S);
    float H  = lz - U / S;
    float lp = -En / T - lz;
    float p  = expf(lp);
    return w2 * (p * (lp + H) / T);
}

// ---------------- kernels ----------------

// dtype sniff (per block) + int32 conversion + degree histogram
__global__ void k_prep(const void* ei) {
    __shared__ int s_is64;
    int tid = threadIdx.x;
    if (tid == 0) s_is64 = 1;
    __syncthreads();
    const int* w = (const int*)ei;
    if (tid < 128) {
        int hi = w[2 * tid + 1];
        unsigned lo = (unsigned)w[2 * tid];
        if (hi != 0 || lo >= NN) s_is64 = 0;   // benign race
    }
    __syncthreads();
    int is64 = s_is64;
    int e = blockIdx.x * blockDim.x + tid;
    if (e >= NE) return;
    int s, d;
    if (is64) {
        s = (int)((const long long*)ei)[e];
        d = (int)((const long long*)ei)[NE + e];
    } else {
        s = w[e];
        d = w[NE + e];
    }
    g_src[e] = s;
    g_dst[e] = d;
    atomicAdd(&g_s.degi[d], 1);
}

// --- 3-kernel exclusive scan of degi -> rowp, plus cursors + dinv ---
__global__ void k_scan1() {
    __shared__ int wtot[8], woff[8];
    int i = blockIdx.x * 256 + threadIdx.x;
    int lane = threadIdx.x & 31, wid = threadIdx.x >> 5;
    int v = (i < NN) ? g_s.degi[i] : 0;
    int x = v;
#pragma unroll
    for (int o = 1; o < 32; o <<= 1) {
        int y = __shfl_up_sync(0xffffffffu, x, o);
        if (lane >= o) x += y;
    }
    if (lane == 31) wtot[wid] = x;
    __syncthreads();
    if (threadIdx.x == 0) {
        int r = 0;
#pragma unroll
        for (int k = 0; k < 8; k++) { woff[k] = r; r += wtot[k]; }
        g_bsum[blockIdx.x] = r;
    }
    __syncthreads();
    if (i < NN) g_rowp[i + 1] = x + woff[wid];   // block-local inclusive (temp)
}

__global__ void k_scan2() {
    __shared__ int wtot[8], woff[8];
    int i = threadIdx.x;
    int lane = i & 31, wid = i >> 5;
    int v = (i < NB) ? g_bsum[i] : 0;
    int x = v;
#pragma unroll
    for (int o = 1; o < 32; o <<= 1) {
        int y = __shfl_up_sync(0xffffffffu, x, o);
        if (lane >= o) x += y;
    }
    if (lane == 31) wtot[wid] = x;
    __syncthreads();
    if (i == 0) {
        int r = 0;
#pragma unroll
        for (int k = 0; k < 8; k++) { woff[k] = r; r += wtot[k]; }
    }
    __syncthreads();
    if (i < NB) g_boff[i] = x + woff[wid] - v;   // exclusive
}

__global__ void k_scan3() {
    int i = blockIdx.x * 256 + threadIdx.x;
    if (i >= NN) return;
    int off  = g_boff[blockIdx.x];
    int incl = g_rowp[i + 1] + off;              // global inclusive prefix
    g_rowp[i + 1] = incl;
    int deg = g_s.degi[i];
    g_cur[i] = incl - deg;                       // exclusive = row start
    g_dinv[i] = rsqrtf((float)deg + 1.0f);       // +1 self-loop
    if (i == 0) g_rowp[0] = 0;
}

__global__ void k_fill() {
    int e = blockIdx.x * blockDim.x + threadIdx.x;
    if (e >= NE) return;
    int pos = atomicAdd(&g_cur[g_dst[e]], 1);
    g_csr[pos] = g_src[e];
}

// h = x @ W  (fp32; 64-row tile in smem, W float4 via L1)
__global__ void __launch_bounds__(256) k_gemm(const float* __restrict__ x,
                                              const float* __restrict__ W) {
    __shared__ float xs[64 * DD];
    int row0 = blockIdx.x * 64;
    float4* xs4 = (float4*)xs;
    const float4* x4 = (const float4*)x;
    for (int i = threadIdx.x; i < 64 * 32; i += 256) {
        int r = row0 + (i >> 5);
        xs4[i] = (r < NN) ? x4[r * 32 + (i & 31)] : make_float4(0.f, 0.f, 0.f, 0.f);
    }
    __syncthreads();

    int cg = threadIdx.x & 31;
    int rg = threadIdx.x >> 5;
    const float4* W4 = (const float4*)W;
    float4 acc[8];
#pragma unroll
    for (int i = 0; i < 8; i++) acc[i] = make_float4(0.f, 0.f, 0.f, 0.f);

    const float* xrow = xs + (rg * 8) * DD;
#pragma unroll 8
    for (int k = 0; k < DD; k++) {
        float4 w = __ldg(&W4[k * 32 + cg]);
#pragma unroll
        for (int i = 0; i < 8; i++) {
            float xv = xrow[i * DD + k];
            acc[i].x += xv * w.x;
            acc[i].y += xv * w.y;
            acc[i].z += xv * w.z;
            acc[i].w += xv * w.w;
        }
    }
    float4* h4 = (float4*)g_h;
#pragma unroll
    for (int i = 0; i < 8; i++) {
        int r = row0 + rg * 8 + i;
        if (r < NN) h4[r * 32 + cg] = acc[i];
    }
}

// z[n] = b + dinv_n*(dinv_n*h[n] + sum_in dinv_s*h[s]); write to g_z AND out.
// Warp per node; 6250 blocks * 8 warps = 50000 exactly (no guards).
__global__ void __launch_bounds__(256) k_gatherz(const float* __restrict__ b,
                                                 float* __restrict__ out) {
    int t = blockIdx.x * blockDim.x + threadIdx.x;
    int n = t >> 5, lane = t & 31;
    int beg = g_rowp[n], end = g_rowp[n + 1];
    const float4* h4 = (const float4*)g_h;
    float4 acc = make_float4(0.f, 0.f, 0.f, 0.f);
    for (int base = beg; base < end; base += 32) {
        int idx = base + lane;
        int sv = (idx < end) ? g_csr[idx] : 0;
        float dv = (idx < end) ? g_dinv[sv] : 0.f;
        int cnt = min(32, end - base);
        for (int j = 0; j < cnt; j++) {
            int   ss  = __shfl_sync(0xffffffffu, sv, j);
            float dss = __shfl_sync(0xffffffffu, dv, j);
            float4 hv = __ldg(&h4[ss * 32 + lane]);
            acc.x += dss * hv.x;
            acc.y += dss * hv.y;
            acc.z += dss * hv.z;
            acc.w += dss * hv.w;
        }
    }
    float dd = g_dinv[n];
    float4 hn = __ldg(&h4[n * 32 + lane]);
    float4 bb = __ldg(&((const float4*)b)[lane]);
    float4 z;
    z.x = bb.x + dd * (dd * hn.x + acc.x);
    z.y = bb.y + dd * (dd * hn.y + acc.y);
    z.z = bb.z + dd * (dd * hn.z + acc.z);
    z.w = bb.w + dd * (dd * hn.w + acc.w);
    ((float4*)g_z)[t] = z;
    ((float4*)out)[t] = z;
}

// E[n] = sum_in ||z[s]-z[n]||^2 ; fused global umax reduction.
__global__ void __launch_bounds__(256) k_energy(const float* __restrict__ temp) {
    __shared__ unsigned skey[8];
    int t = blockIdx.x * blockDim.x + threadIdx.x;
    int n = t >> 5, lane = t & 31, wid = threadIdx.x >> 5;
    int beg = g_rowp[n], end = g_rowp[n + 1];
    const float4* z4 = (const float4*)g_z;
    float4 zd = z4[n * 32 + lane];
    float accE = 0.f;
    for (int base = beg; base < end; base += 32) {
        int idx = base + lane;
        int sv = (idx < end) ? g_csr[idx] : 0;
        int cnt = min(32, end - base);
        for (int j = 0; j < cnt; j++) {
            int ss = __shfl_sync(0xffffffffu, sv, j);
            float4 zs = __ldg(&z4[ss * 32 + lane]);
            float dx = zs.x - zd.x, dy = zs.y - zd.y;
            float dz = zs.z - zd.z, dw = zs.w - zd.w;
            accE += dx * dx + dy * dy + dz * dz + dw * dw;
        }
    }
    float Et = warp_sum(accE);
    unsigned key = 0u;
    if (lane == 0) {
        g_s.E[n] = Et;
        key = f2key(-Et / temp[0]);
        skey[wid] = key;
    }
    __syncthreads();
    if (threadIdx.x == 0) {
        unsigned mx = 0u;
#pragma unroll
        for (int k = 0; k < 8; k++) mx = max(mx, skey[k]);
        atomicMax(&g_s.umax, mx);
    }
}

// S = sum e^{u-m}, U = sum e^{u-m}*u
__global__ void k_sum(const float* __restrict__ temp) {
    __shared__ float sS[8], sU[8];
    int i = blockIdx.x * blockDim.x + threadIdx.x;
    int lane = threadIdx.x & 31, wid = threadIdx.x >> 5;
    float vS = 0.f, vU = 0.f;
    if (i < NN) {
        float u = -g_s.E[i] / temp[0];
        float ex = expf(u - key2f(g_s.umax));
        vS = ex;
        vU = ex * u;
    }
    vS = warp_sum(vS);
    vU = warp_sum(vU);
    if (lane == 0) { sS[wid] = vS; sU[wid] = vU; }
    __syncthreads();
    if (threadIdx.x == 0) {
        float aS = 0.f, aU = 0.f;
#pragma unroll
        for (int k = 0; k < 8; k++) { aS += sS[k]; aU += sU[k]; }
        atomicAdd(&g_s.S, aS);
        atomicAdd(&g_s.U, aU);
    }
}

// Active-node queue: nodes with nonzero coef (p did not underflow).
__global__ void k_qbuild(const float* __restrict__ temp,
                         const float* __restrict__ weight) {
    int n = blockIdx.x * blockDim.x + threadIdx.x;
    if (n >= NN) return;
    float c = coef_of(g_s.E[n], temp[0], key2f(g_s.umax),
                      g_s.S, g_s.U, 2.0f * weight[0]);
    if (c != 0.0f) {
        int i = atomicAdd(&g_s.qn, 1);
        g_q[i] = n;
    }
}

// Gradient: for each active node d, out[s] += c*(z_s - z_d) per in-edge,
// out[d] -= c * sum(z_s - z_d).  Warp per queue entry, persistent.
__global__ void k_gradq(const float* __restrict__ temp,
                        const float* __restrict__ weight,
                        float* __restrict__ out) {
    int gw = (blockIdx.x * blockDim.x + threadIdx.x) >> 5;
    int nw = (gridDim.x * blockDim.x) >> 5;
    int lane = threadIdx.x & 31;
    int qn = g_s.qn;
    float T = temp[0], m = key2f(g_s.umax);
    float S = g_s.S, U = g_s.U, w2 = 2.0f * weight[0];
    const float4* z4 = (const float4*)g_z;
    for (int i = gw; i < qn; i += nw) {
        int d = g_q[i];
        float c = coef_of(g_s.E[d], T, m, S, U, w2);
        float4 zd = z4[d * 32 + lane];
        float4 sum = make_float4(0.f, 0.f, 0.f, 0.f);
        int beg = g_rowp[d], end = g_rowp[d + 1];
        for (int base = beg; base < end; base += 32) {
            int idx = base + lane;
            int sv = (idx < end) ? g_csr[idx] : 0;
            int cnt = min(32, end - base);
            for (int j = 0; j < cnt; j++) {
                int ss = __shfl_sync(0xffffffffu, sv, j);
                float4 zs = z4[ss * 32 + lane];
                float dx = zs.x - zd.x, dy = zs.y - zd.y;
                float dz = zs.z - zd.z, dw = zs.w - zd.w;
                red_add_v4(&out[ss * DD + lane * 4], c * dx, c * dy, c * dz, c * dw);
                sum.x += dx; sum.y += dy; sum.z += dz; sum.w += dw;
            }
        }
        red_add_v4(&out[d * DD + lane * 4], -c * sum.x, -c * sum.y,
                   -c * sum.z, -c * sum.w);
    }
}

// ---------------- launch ----------------
extern "C" void kernel_launch(void* const* d_in, const int* in_sizes, int n_in,
                              void* d_out, int out_size) {
    const float* x      = (const float*)d_in[0];
    const void*  ei     = d_in[1];
    const float* weight = (const float*)d_in[2];
    const float* temp   = (const float*)d_in[3];
    const float* W      = (const float*)d_in[4];
    const float* b      = (const float*)d_in[5];
    float* out = (float*)d_out;

    void* scr = nullptr;
    cudaGetSymbolAddress(&scr, g_s);
    cudaMemsetAsync(scr, 0, sizeof(Scr));

    const int TB = 256;
    const int gE  = (NE + TB - 1) / TB;        // 2500
    const int gW  = (NN * 32) / TB;            // 6250 (warp per node, exact)
    const int gN  = NB;                        // 196

    k_prep   <<<gE, TB>>>(ei);
    k_gemm   <<<(NN + 63) / 64, TB>>>(x, W);
    k_scan1  <<<gN, TB>>>();
    k_scan2  <<<1, TB>>>();
    k_scan3  <<<gN, TB>>>();
    k_fill   <<<gE, TB>>>();
    k_gatherz<<<gW, TB>>>(b, out);
    k_energy <<<gW, TB>>>(temp);
    k_sum    <<<gN, TB>>>(temp);
    k_qbuild <<<gN, TB>>>(temp, weight);
    k_gradq  <<<64, TB>>>(temp, weight, out);
}

// round 11
// speedup vs baseline: 1.7688x; 1.0692x over previous
#include <cuda_runtime.h>

#define NN 50000
#define NE 640000
#define DD 128
#define NB 196            // ceil(NN/256)

// ---------------- scratch (device globals: allocation-free) ----------------
struct Scr {               // zeroed by one cudaMemsetAsync each call
    int      degi[NN];     // in-degree histogram
    float    E[NN];        // per-node Dirichlet energy
    float    S;            // sum exp(u - m)
    float    U;            // sum exp(u - m) * u
    unsigned umax;         // ordered-key max of u = -E/T (0 below all keys)
    int      qn;           // active-node queue count
};
__device__ Scr   g_s;
__device__ float g_dinv[NN];
__device__ float g_h[NN * DD];     // x @ W
__device__ float g_z[NN * DD];     // GCN output
__device__ int   g_src[NE];        // int32 edge copies
__device__ int   g_dst[NE];
__device__ int   g_rowp[NN + 1];   // CSR row pointer (by dst)
__device__ int   g_cur[NN];        // fill cursors
__device__ int   g_csr[NE];        // src ids grouped by dst
__device__ int   g_bsum[NB];       // scan partials
__device__ int   g_boff[NB];
__device__ int   g_q[NN];          // active node queue

// ---------------- helpers ----------------
__device__ __forceinline__ unsigned f2key(float f) {
    unsigned b = __float_as_uint(f);
    return b ^ ((b >> 31) ? 0xFFFFFFFFu : 0x80000000u);
}
__device__ __forceinline__ float key2f(unsigned k) {
    unsigned b = (k >> 31) ? (k ^ 0x80000000u) : ~k;
    return __uint_as_float(b);
}
__device__ __forceinline__ void red_add_v4(float* p, float a, float b, float c, float d) {
    asm volatile("red.global.add.v4.f32 [%0], {%1,%2,%3,%4};"
                 :: "l"(p), "f"(a), "f"(b), "f"(c), "f"(d) : "memory");
}
__device__ __forceinline__ float warp_sum(float v) {
#pragma unroll
    for (int o = 16; o; o >>= 1) v += __shfl_xor_sync(0xffffffffu, v, o);
    return v;
}
__device__ __forceinline__ unsigned long long packf2(float lo, float hi) {
    unsigned long long r;
    asm("mov.b64 %0, {%1, %2};" : "=l"(r) : "f"(lo), "f"(hi));
    return r;
}
__device__ __forceinline__ void unpackf2(float& lo, float& hi, unsigned long long v) {
    asm("mov.b64 {%0, %1}, %2;" : "=f"(lo), "=f"(hi) : "l"(v));
}
__device__ __forceinline__ void ffma2(unsigned long long& acc,
                                      unsigned long long a, unsigned long long b) {
    asm("fma.rn.f32x2 %0, %1, %2, %0;" : "+l"(acc) : "l"(a), "l"(b));
}
// coef[n] = 2*weight*lambda_n, lambda = p(log p + H)/T; exact 0 when p underflows.
__device__ __forceinline__ float coef_of(float En, float T, float m,
                                         float S, float U, float w2) {
    float lz = m + logf(S);
    float H  = lz - U / S;
    float lp = -En / T - lz;
    float p  = expf(lp);
    return w2 * (p * (lp + H) / T);
}

// ---------------- kernels ----------------

// dtype sniff (per block) + int32 conversion + degree histogram
__global__ void k_prep(const void* ei) {
    __shared__ int s_is64;
    int tid = threadIdx.x;
    if (tid == 0) s_is64 = 1;
    __syncthreads();
    const int* w = (const int*)ei;
    if (tid < 128) {
        int hi = w[2 * tid + 1];
        unsigned lo = (unsigned)w[2 * tid];
        if (hi != 0 || lo >= NN) s_is64 = 0;   // benign race
    }
    __syncthreads();
    int is64 = s_is64;
    int e = blockIdx.x * blockDim.x + tid;
    if (e >= NE) return;
    int s, d;
    if (is64) {
        s = (int)((const long long*)ei)[e];
        d = (int)((const long long*)ei)[NE + e];
    } else {
        s = w[e];
        d = w[NE + e];
    }
    g_src[e] = s;
    g_dst[e] = d;
    atomicAdd(&g_s.degi[d], 1);
}

// --- 3-kernel exclusive scan of degi -> rowp, plus cursors + dinv ---
__global__ void k_scan1() {
    __shared__ int wtot[8], woff[8];
    int i = blockIdx.x * 256 + threadIdx.x;
    int lane = threadIdx.x & 31, wid = threadIdx.x >> 5;
    int v = (i < NN) ? g_s.degi[i] : 0;
    int x = v;
#pragma unroll
    for (int o = 1; o < 32; o <<= 1) {
        int y = __shfl_up_sync(0xffffffffu, x, o);
        if (lane >= o) x += y;
    }
    if (lane == 31) wtot[wid] = x;
    __syncthreads();
    if (threadIdx.x == 0) {
        int r = 0;
#pragma unroll
        for (int k = 0; k < 8; k++) { woff[k] = r; r += wtot[k]; }
        g_bsum[blockIdx.x] = r;
    }
    __syncthreads();
    if (i < NN) g_rowp[i + 1] = x + woff[wid];   // block-local inclusive (temp)
}

__global__ void k_scan2() {
    __shared__ int wtot[8], woff[8];
    int i = threadIdx.x;
    int lane = i & 31, wid = i >> 5;
    int v = (i < NB) ? g_bsum[i] : 0;
    int x = v;
#pragma unroll
    for (int o = 1; o < 32; o <<= 1) {
        int y = __shfl_up_sync(0xffffffffu, x, o);
        if (lane >= o) x += y;
    }
    if (lane == 31) wtot[wid] = x;
    __syncthreads();
    if (i == 0) {
        int r = 0;
#pragma unroll
        for (int k = 0; k < 8; k++) { woff[k] = r; r += wtot[k]; }
    }
    __syncthreads();
    if (i < NB) g_boff[i] = x + woff[wid] - v;   // exclusive
}

__global__ void k_scan3() {
    int i = blockIdx.x * 256 + threadIdx.x;
    if (i >= NN) return;
    int off  = g_boff[blockIdx.x];
    int incl = g_rowp[i + 1] + off;              // global inclusive prefix
    g_rowp[i + 1] = incl;
    int deg = g_s.degi[i];
    g_cur[i] = incl - deg;                       // exclusive = row start
    g_dinv[i] = rsqrtf((float)deg + 1.0f);       // +1 self-loop
    if (i == 0) g_rowp[0] = 0;
}

__global__ void k_fill() {
    int e = blockIdx.x * blockDim.x + threadIdx.x;
    if (e >= NE) return;
    int pos = atomicAdd(&g_cur[g_dst[e]], 1);
    g_csr[pos] = g_src[e];
}

// h = x @ W  via packed fma.rn.f32x2 (FFMA2): 2 fp32 FMA lanes per issue.
// Thread: 4 output cols (2 col-pairs) x 8 rows. Bit-exact fp32.
__global__ void __launch_bounds__(256) k_gemm(const float* __restrict__ x,
                                              const float* __restrict__ W) {
    __shared__ float xs[64 * DD];
    int row0 = blockIdx.x * 64;
    float4* xs4 = (float4*)xs;
    const float4* x4 = (const float4*)x;
    for (int i = threadIdx.x; i < 64 * 32; i += 256) {
        int r = row0 + (i >> 5);
        xs4[i] = (r < NN) ? x4[r * 32 + (i & 31)] : make_float4(0.f, 0.f, 0.f, 0.f);
    }
    __syncthreads();

    int cg = threadIdx.x & 31;   // col-pairs (4cg,4cg+1) and (4cg+2,4cg+3)
    int rg = threadIdx.x >> 5;   // 8 rows
    const float4* W4 = (const float4*)W;
    unsigned long long accA[8], accB[8];
#pragma unroll
    for (int i = 0; i < 8; i++) { accA[i] = 0ull; accB[i] = 0ull; }

    const float* xrow = xs + (rg * 8) * DD;
#pragma unroll 4
    for (int k = 0; k < DD; k++) {
        float4 w = __ldg(&W4[k * 32 + cg]);
        unsigned long long wA = packf2(w.x, w.y);
        unsigned long long wB = packf2(w.z, w.w);
#pragma unroll
        for (int i = 0; i < 8; i++) {
            float xv = xrow[i * DD + k];
            unsigned long long xp = packf2(xv, xv);
            ffma2(accA[i], xp, wA);
            ffma2(accB[i], xp, wB);
        }
    }
    float4* h4 = (float4*)g_h;
#pragma unroll
    for (int i = 0; i < 8; i++) {
        int r = row0 + rg * 8 + i;
        if (r < NN) {
            float4 o;
            unpackf2(o.x, o.y, accA[i]);
            unpackf2(o.z, o.w, accB[i]);
            h4[r * 32 + cg] = o;
        }
    }
}

// z[n] = b + dinv_n*(dinv_n*h[n] + sum_in dinv_s*h[s]); write to g_z AND out.
// Warp per node; 4-wide unrolled gather for MLP.
__global__ void __launch_bounds__(256) k_gatherz(const float* __restrict__ b,
                                                 float* __restrict__ out) {
    int t = blockIdx.x * blockDim.x + threadIdx.x;
    int n = t >> 5, lane = t & 31;
    int beg = g_rowp[n], end = g_rowp[n + 1];
    const float4* h4 = (const float4*)g_h;
    float4 a0 = make_float4(0.f, 0.f, 0.f, 0.f);
    float4 a1 = a0, a2 = a0, a3 = a0;
    int j = beg;
    for (; j + 4 <= end; j += 4) {
        int s0 = g_csr[j], s1 = g_csr[j + 1], s2 = g_csr[j + 2], s3 = g_csr[j + 3];
        float d0 = g_dinv[s0], d1 = g_dinv[s1], d2 = g_dinv[s2], d3 = g_dinv[s3];
        float4 v0 = __ldg(&h4[s0 * 32 + lane]);
        float4 v1 = __ldg(&h4[s1 * 32 + lane]);
        float4 v2 = __ldg(&h4[s2 * 32 + lane]);
        float4 v3 = __ldg(&h4[s3 * 32 + lane]);
        a0.x += d0 * v0.x; a0.y += d0 * v0.y; a0.z += d0 * v0.z; a0.w += d0 * v0.w;
        a1.x += d1 * v1.x; a1.y += d1 * v1.y; a1.z += d1 * v1.z; a1.w += d1 * v1.w;
        a2.x += d2 * v2.x; a2.y += d2 * v2.y; a2.z += d2 * v2.z; a2.w += d2 * v2.w;
        a3.x += d3 * v3.x; a3.y += d3 * v3.y; a3.z += d3 * v3.z; a3.w += d3 * v3.w;
    }
    for (; j < end; j++) {
        int s0 = g_csr[j];
        float d0 = g_dinv[s0];
        float4 v0 = __ldg(&h4[s0 * 32 + lane]);
        a0.x += d0 * v0.x; a0.y += d0 * v0.y; a0.z += d0 * v0.z; a0.w += d0 * v0.w;
    }
    float4 acc;
    acc.x = (a0.x + a1.x) + (a2.x + a3.x);
    acc.y = (a0.y + a1.y) + (a2.y + a3.y);
    acc.z = (a0.z + a1.z) + (a2.z + a3.z);
    acc.w = (a0.w + a1.w) + (a2.w + a3.w);

    float dd = g_dinv[n];
    float4 hn = __ldg(&h4[n * 32 + lane]);
    float4 bb = __ldg(&((const float4*)b)[lane]);
    float4 z;
    z.x = bb.x + dd * (dd * hn.x + acc.x);
    z.y = bb.y + dd * (dd * hn.y + acc.y);
    z.z = bb.z + dd * (dd * hn.z + acc.z);
    z.w = bb.w + dd * (dd * hn.w + acc.w);
    ((float4*)g_z)[t] = z;
    ((float4*)out)[t] = z;
}

// E[n] = sum_in ||z[s]-z[n]||^2 ; fused global umax reduction. 4-wide gather.
__global__ void __launch_bounds__(256) k_energy(const float* __restrict__ temp) {
    __shared__ unsigned skey[8];
    int t = blockIdx.x * blockDim.x + threadIdx.x;
    int n = t >> 5, lane = t & 31, wid = threadIdx.x >> 5;
    int beg = g_rowp[n], end = g_rowp[n + 1];
    const float4* z4 = (const float4*)g_z;
    float4 zd = z4[n * 32 + lane];
    float e0 = 0.f, e1 = 0.f, e2 = 0.f, e3 = 0.f;
    int j = beg;
    for (; j + 4 <= end; j += 4) {
        int s0 = g_csr[j], s1 = g_csr[j + 1], s2 = g_csr[j + 2], s3 = g_csr[j + 3];
        float4 v0 = __ldg(&z4[s0 * 32 + lane]);
        float4 v1 = __ldg(&z4[s1 * 32 + lane]);
        float4 v2 = __ldg(&z4[s2 * 32 + lane]);
        float4 v3 = __ldg(&z4[s3 * 32 + lane]);
        float x0 = v0.x - zd.x, y0 = v0.y - zd.y, u0 = v0.z - zd.z, w0 = v0.w - zd.w;
        float x1 = v1.x - zd.x, y1 = v1.y - zd.y, u1 = v1.z - zd.z, w1 = v1.w - zd.w;
        float x2 = v2.x - zd.x, y2 = v2.y - zd.y, u2 = v2.z - zd.z, w2 = v2.w - zd.w;
        float x3 = v3.x - zd.x, y3 = v3.y - zd.y, u3 = v3.z - zd.z, w3 = v3.w - zd.w;
        e0 += x0 * x0 + y0 * y0 + u0 * u0 + w0 * w0;
        e1 += x1 * x1 + y1 * y1 + u1 * u1 + w1 * w1;
        e2 += x2 * x2 + y2 * y2 + u2 * u2 + w2 * w2;
        e3 += x3 * x3 + y3 * y3 + u3 * u3 + w3 * w3;
    }
    for (; j < end; j++) {
        int s0 = g_csr[j];
        float4 v0 = __ldg(&z4[s0 * 32 + lane]);
        float x0 = v0.x - zd.x, y0 = v0.y - zd.y, u0 = v0.z - zd.z, w0 = v0.w - zd.w;
        e0 += x0 * x0 + y0 * y0 + u0 * u0 + w0 * w0;
    }
    float Et = warp_sum((e0 + e1) + (e2 + e3));
    if (lane == 0) {
        g_s.E[n] = Et;
        skey[wid] = f2key(-Et / temp[0]);
    }
    __syncthreads();
    if (threadIdx.x == 0) {
        unsigned mx = 0u;
#pragma unroll
        for (int k = 0; k < 8; k++) mx = max(mx, skey[k]);
        atomicMax(&g_s.umax, mx);
    }
}

// S = sum e^{u-m}, U = sum e^{u-m}*u
__global__ void k_sum(const float* __restrict__ temp) {
    __shared__ float sS[8], sU[8];
    int i = blockIdx.x * blockDim.x + threadIdx.x;
    int lane = threadIdx.x & 31, wid = threadIdx.x >> 5;
    float vS = 0.f, vU = 0.f;
    if (i < NN) {
        float u = -g_s.E[i] / temp[0];
        float ex = expf(u - key2f(g_s.umax));
        vS = ex;
        vU = ex * u;
    }
    vS = warp_sum(vS);
    vU = warp_sum(vU);
    if (lane == 0) { sS[wid] = vS; sU[wid] = vU; }
    __syncthreads();
    if (threadIdx.x == 0) {
        float aS = 0.f, aU = 0.f;
#pragma unroll
        for (int k = 0; k < 8; k++) { aS += sS[k]; aU += sU[k]; }
        atomicAdd(&g_s.S, aS);
        atomicAdd(&g_s.U, aU);
    }
}

// Active-node queue: nodes with nonzero coef (p did not underflow).
__global__ void k_qbuild(const float* __restrict__ temp,
                         const float* __restrict__ weight) {
    int n = blockIdx.x * blockDim.x + threadIdx.x;
    if (n >= NN) return;
    float c = coef_of(g_s.E[n], temp[0], key2f(g_s.umax),
                      g_s.S, g_s.U, 2.0f * weight[0]);
    if (c != 0.0f) {
        int i = atomicAdd(&g_s.qn, 1);
        g_q[i] = n;
    }
}

// Gradient: for each active node d, out[s] += c*(z_s - z_d) per in-edge,
// out[d] -= c * sum(z_s - z_d).  Warp per queue entry, persistent.
__global__ void k_gradq(const float* __restrict__ temp,
                        const float* __restrict__ weight,
                        float* __restrict__ out) {
    int gw = (blockIdx.x * blockDim.x + threadIdx.x) >> 5;
    int nw = (gridDim.x * blockDim.x) >> 5;
    int lane = threadIdx.x & 31;
    int qn = g_s.qn;
    float T = temp[0], m = key2f(g_s.umax);
    float S = g_s.S, U = g_s.U, w2 = 2.0f * weight[0];
    const float4* z4 = (const float4*)g_z;
    for (int i = gw; i < qn; i += nw) {
        int d = g_q[i];
        float c = coef_of(g_s.E[d], T, m, S, U, w2);
        float4 zd = z4[d * 32 + lane];
        float4 sum = make_float4(0.f, 0.f, 0.f, 0.f);
        int beg = g_rowp[d], end = g_rowp[d + 1];
        for (int j = beg; j < end; j++) {
            int ss = g_csr[j];
            float4 zs = z4[ss * 32 + lane];
            float dx = zs.x - zd.x, dy = zs.y - zd.y;
            float dz = zs.z - zd.z, dw = zs.w - zd.w;
            red_add_v4(&out[ss * DD + lane * 4], c * dx, c * dy, c * dz, c * dw);
            sum.x += dx; sum.y += dy; sum.z += dz; sum.w += dw;
        }
        red_add_v4(&out[d * DD + lane * 4], -c * sum.x, -c * sum.y,
                   -c * sum.z, -c * sum.w);
    }
}

// ---------------- launch ----------------
extern "C" void kernel_launch(void* const* d_in, const int* in_sizes, int n_in,
                              void* d_out, int out_size) {
    const float* x      = (const float*)d_in[0];
    const void*  ei     = d_in[1];
    const float* weight = (const float*)d_in[2];
    const float* temp   = (const float*)d_in[3];
    const float* W      = (const float*)d_in[4];
    const float* b      = (const float*)d_in[5];
    float* out = (float*)d_out;

    void* scr = nullptr;
    cudaGetSymbolAddress(&scr, g_s);
    cudaMemsetAsync(scr, 0, sizeof(Scr));

    const int TB = 256;
    const int gE = (NE + TB - 1) / TB;        // 2500
    const int gW = (NN * 32) / TB;            // 6250 (warp per node, exact)
    const int gN = NB;                        // 196

    k_prep   <<<gE, TB>>>(ei);
    k_gemm   <<<(NN + 63) / 64, TB>>>(x, W);
    k_scan1  <<<gN, TB>>>();
    k_scan2  <<<1, TB>>>();
    k_scan3  <<<gN, TB>>>();
    k_fill   <<<gE, TB>>>();
    k_gatherz<<<gW, TB>>>(b, out);
    k_energy <<<gW, TB>>>(temp);
    k_sum    <<<gN, TB>>>(temp);
    k_qbuild <<<gN, TB>>>(temp, weight);
    k_gradq  <<<64, TB>>>(temp, weight, out);
}

// round 12
// speedup vs baseline: 2.0802x; 1.1760x over previous
#include <cuda_runtime.h>

#define NN 50000
#define NE 640000
#define DD 128
#define NB 196            // ceil(NN/256)

// ---------------- scratch (device globals: allocation-free) ----------------
struct Scr {               // zeroed by one cudaMemsetAsync each call
    int      degi[NN];     // in-degree histogram
    float    E[NN];        // per-node Dirichlet energy
    float    S;            // sum exp(u - m)
    float    U;            // sum exp(u - m) * u
    unsigned umax;         // ordered-key max of u = -E/T (0 below all keys)
};
__device__ Scr   g_s;
__device__ float g_dinv[NN];
__device__ float g_h[NN * DD];     // x @ W
__device__ float g_z[NN * DD];     // GCN output
__device__ int   g_rowp[NN + 1];   // CSR row pointer (by dst)
__device__ int   g_cur[NN];        // fill cursors
__device__ int   g_csr[NE];        // src ids grouped by dst
__device__ int   g_bsum[NB];       // scan partials
__device__ int   g_boff[NB];

// ---------------- helpers ----------------
__device__ __forceinline__ unsigned f2key(float f) {
    unsigned b = __float_as_uint(f);
    return b ^ ((b >> 31) ? 0xFFFFFFFFu : 0x80000000u);
}
__device__ __forceinline__ float key2f(unsigned k) {
    unsigned b = (k >> 31) ? (k ^ 0x80000000u) : ~k;
    return __uint_as_float(b);
}
__device__ __forceinline__ void red_add_v4(float* p, float a, float b, float c, float d) {
    asm volatile("red.global.add.v4.f32 [%0], {%1,%2,%3,%4};"
                 :: "l"(p), "f"(a), "f"(b), "f"(c), "f"(d) : "memory");
}
__device__ __forceinline__ float warp_sum(float v) {
#pragma unroll
    for (int o = 16; o; o >>= 1) v += __shfl_xor_sync(0xffffffffu, v, o);
    return v;
}
__device__ __forceinline__ unsigned long long packf2(float lo, float hi) {
    unsigned long long r;
    asm("mov.b64 %0, {%1, %2};" : "=l"(r) : "f"(lo), "f"(hi));
    return r;
}
__device__ __forceinline__ void unpackf2(float& lo, float& hi, unsigned long long v) {
    asm("mov.b64 {%0, %1}, %2;" : "=f"(lo), "=f"(hi) : "l"(v));
}
__device__ __forceinline__ void ffma2(unsigned long long& acc,
                                      unsigned long long a, unsigned long long b) {
    asm("fma.rn.f32x2 %0, %1, %2, %0;" : "+l"(acc) : "l"(a), "l"(b));
}
// coef[n] = 2*weight*lambda_n, lambda = p(log p + H)/T; exact 0 when p underflows.
__device__ __forceinline__ float coef_of(float En, float T, float m,
                                         float S, float U, float w2) {
    float lz = m + logf(S);
    float H  = lz - U / S;
    float lp = -En / T - lz;
    float p  = expf(lp);
    return w2 * (p * (lp + H) / T);
}
// per-block int64/int32 sniff: int64 little-endian with idx<NN
// => odd 32-bit words of first 128 pairs are all 0.
__device__ __forceinline__ int sniff64(const int* w) {
    __shared__ int s_is64;
    if (threadIdx.x == 0) s_is64 = 1;
    __syncthreads();
    if (threadIdx.x < 128) {
        int hi = w[2 * threadIdx.x + 1];
        unsigned lo = (unsigned)w[2 * threadIdx.x];
        if (hi != 0 || lo >= NN) s_is64 = 0;   // benign race
    }
    __syncthreads();
    return s_is64;
}
__device__ __forceinline__ int2 edge_of(const void* ei, int e, int is64) {
    int2 r;
    if (is64) {
        r.x = (int)((const long long*)ei)[e];
        r.y = (int)((const long long*)ei)[NE + e];
    } else {
        r.x = ((const int*)ei)[e];
        r.y = ((const int*)ei)[NE + e];
    }
    return r;
}

// ---------------- kernels ----------------

// in-degree histogram
__global__ void k_prep(const void* ei) {
    int is64 = sniff64((const int*)ei);
    int e = blockIdx.x * blockDim.x + threadIdx.x;
    if (e >= NE) return;
    int d = is64 ? (int)((const long long*)ei)[NE + e] : ((const int*)ei)[NE + e];
    atomicAdd(&g_s.degi[d], 1);
}

// --- 3-kernel exclusive scan of degi -> rowp, plus cursors + dinv ---
__global__ void k_scan1() {
    __shared__ int wtot[8], woff[8];
    int i = blockIdx.x * 256 + threadIdx.x;
    int lane = threadIdx.x & 31, wid = threadIdx.x >> 5;
    int v = (i < NN) ? g_s.degi[i] : 0;
    int x = v;
#pragma unroll
    for (int o = 1; o < 32; o <<= 1) {
        int y = __shfl_up_sync(0xffffffffu, x, o);
        if (lane >= o) x += y;
    }
    if (lane == 31) wtot[wid] = x;
    __syncthreads();
    if (threadIdx.x == 0) {
        int r = 0;
#pragma unroll
        for (int k = 0; k < 8; k++) { woff[k] = r; r += wtot[k]; }
        g_bsum[blockIdx.x] = r;
    }
    __syncthreads();
    if (i < NN) g_rowp[i + 1] = x + woff[wid];   // block-local inclusive (temp)
}

__global__ void k_scan2() {
    __shared__ int wtot[8], woff[8];
    int i = threadIdx.x;
    int lane = i & 31, wid = i >> 5;
    int v = (i < NB) ? g_bsum[i] : 0;
    int x = v;
#pragma unroll
    for (int o = 1; o < 32; o <<= 1) {
        int y = __shfl_up_sync(0xffffffffu, x, o);
        if (lane >= o) x += y;
    }
    if (lane == 31) wtot[wid] = x;
    __syncthreads();
    if (i == 0) {
        int r = 0;
#pragma unroll
        for (int k = 0; k < 8; k++) { woff[k] = r; r += wtot[k]; }
    }
    __syncthreads();
    if (i < NB) g_boff[i] = x + woff[wid] - v;   // exclusive
}

__global__ void k_scan3() {
    int i = blockIdx.x * 256 + threadIdx.x;
    if (i >= NN) return;
    int off  = g_boff[blockIdx.x];
    int incl = g_rowp[i + 1] + off;              // global inclusive prefix
    g_rowp[i + 1] = incl;
    int deg = g_s.degi[i];
    g_cur[i] = incl - deg;                       // exclusive = row start
    g_dinv[i] = rsqrtf((float)deg + 1.0f);       // +1 self-loop
    if (i == 0) g_rowp[0] = 0;
}

__global__ void k_fill(const void* ei) {
    int is64 = sniff64((const int*)ei);
    int e = blockIdx.x * blockDim.x + threadIdx.x;
    if (e >= NE) return;
    int2 sd = edge_of(ei, e, is64);
    int pos = atomicAdd(&g_cur[sd.y], 1);
    g_csr[pos] = sd.x;
}

// h = x @ W  via packed fma.rn.f32x2 (FFMA2). Bit-exact fp32.
__global__ void __launch_bounds__(256) k_gemm(const float* __restrict__ x,
                                              const float* __restrict__ W) {
    __shared__ float xs[64 * DD];
    int row0 = blockIdx.x * 64;
    float4* xs4 = (float4*)xs;
    const float4* x4 = (const float4*)x;
    for (int i = threadIdx.x; i < 64 * 32; i += 256) {
        int r = row0 + (i >> 5);
        xs4[i] = (r < NN) ? x4[r * 32 + (i & 31)] : make_float4(0.f, 0.f, 0.f, 0.f);
    }
    __syncthreads();

    int cg = threadIdx.x & 31;
    int rg = threadIdx.x >> 5;
    const float4* W4 = (const float4*)W;
    unsigned long long accA[8], accB[8];
#pragma unroll
    for (int i = 0; i < 8; i++) { accA[i] = 0ull; accB[i] = 0ull; }

    const float* xrow = xs + (rg * 8) * DD;
#pragma unroll 4
    for (int k = 0; k < DD; k++) {
        float4 w = __ldg(&W4[k * 32 + cg]);
        unsigned long long wA = packf2(w.x, w.y);
        unsigned long long wB = packf2(w.z, w.w);
#pragma unroll
        for (int i = 0; i < 8; i++) {
            float xv = xrow[i * DD + k];
            unsigned long long xp = packf2(xv, xv);
            ffma2(accA[i], xp, wA);
            ffma2(accB[i], xp, wB);
        }
    }
    float4* h4 = (float4*)g_h;
#pragma unroll
    for (int i = 0; i < 8; i++) {
        int r = row0 + rg * 8 + i;
        if (r < NN) {
            float4 o;
            unpackf2(o.x, o.y, accA[i]);
            unpackf2(o.z, o.w, accB[i]);
            h4[r * 32 + cg] = o;
        }
    }
}

// z[n] = b + dinv_n*(dinv_n*h[n] + sum_in dinv_s*h[s]); write g_z AND out.
__global__ void __launch_bounds__(256) k_gatherz(const float* __restrict__ b,
                                                 float* __restrict__ out) {
    int t = blockIdx.x * blockDim.x + threadIdx.x;
    int n = t >> 5, lane = t & 31;
    int beg = g_rowp[n], end = g_rowp[n + 1];
    const float4* h4 = (const float4*)g_h;
    float4 a0 = make_float4(0.f, 0.f, 0.f, 0.f);
    float4 a1 = a0, a2 = a0, a3 = a0;
    int j = beg;
    for (; j + 4 <= end; j += 4) {
        int s0 = g_csr[j], s1 = g_csr[j + 1], s2 = g_csr[j + 2], s3 = g_csr[j + 3];
        float d0 = g_dinv[s0], d1 = g_dinv[s1], d2 = g_dinv[s2], d3 = g_dinv[s3];
        float4 v0 = __ldg(&h4[s0 * 32 + lane]);
        float4 v1 = __ldg(&h4[s1 * 32 + lane]);
        float4 v2 = __ldg(&h4[s2 * 32 + lane]);
        float4 v3 = __ldg(&h4[s3 * 32 + lane]);
        a0.x += d0 * v0.x; a0.y += d0 * v0.y; a0.z += d0 * v0.z; a0.w += d0 * v0.w;
        a1.x += d1 * v1.x; a1.y += d1 * v1.y; a1.z += d1 * v1.z; a1.w += d1 * v1.w;
        a2.x += d2 * v2.x; a2.y += d2 * v2.y; a2.z += d2 * v2.z; a2.w += d2 * v2.w;
        a3.x += d3 * v3.x; a3.y += d3 * v3.y; a3.z += d3 * v3.z; a3.w += d3 * v3.w;
    }
    for (; j < end; j++) {
        int s0 = g_csr[j];
        float d0 = g_dinv[s0];
        float4 v0 = __ldg(&h4[s0 * 32 + lane]);
        a0.x += d0 * v0.x; a0.y += d0 * v0.y; a0.z += d0 * v0.z; a0.w += d0 * v0.w;
    }
    float4 acc;
    acc.x = (a0.x + a1.x) + (a2.x + a3.x);
    acc.y = (a0.y + a1.y) + (a2.y + a3.y);
    acc.z = (a0.z + a1.z) + (a2.z + a3.z);
    acc.w = (a0.w + a1.w) + (a2.w + a3.w);

    float dd = g_dinv[n];
    float4 hn = __ldg(&h4[n * 32 + lane]);
    float4 bb = __ldg(&((const float4*)b)[lane]);
    float4 z;
    z.x = bb.x + dd * (dd * hn.x + acc.x);
    z.y = bb.y + dd * (dd * hn.y + acc.y);
    z.z = bb.z + dd * (dd * hn.z + acc.z);
    z.w = bb.w + dd * (dd * hn.w + acc.w);
    ((float4*)g_z)[t] = z;
    ((float4*)out)[t] = z;
}

// E[n] = sum_in ||z[s]-z[n]||^2 ; fused global umax reduction.
__global__ void __launch_bounds__(256) k_energy(const float* __restrict__ temp) {
    __shared__ unsigned skey[8];
    int t = blockIdx.x * blockDim.x + threadIdx.x;
    int n = t >> 5, lane = t & 31, wid = threadIdx.x >> 5;
    int beg = g_rowp[n], end = g_rowp[n + 1];
    const float4* z4 = (const float4*)g_z;
    float4 zd = z4[n * 32 + lane];
    float e0 = 0.f, e1 = 0.f, e2 = 0.f, e3 = 0.f;
    int j = beg;
    for (; j + 4 <= end; j += 4) {
        int s0 = g_csr[j], s1 = g_csr[j + 1], s2 = g_csr[j + 2], s3 = g_csr[j + 3];
        float4 v0 = __ldg(&z4[s0 * 32 + lane]);
        float4 v1 = __ldg(&z4[s1 * 32 + lane]);
        float4 v2 = __ldg(&z4[s2 * 32 + lane]);
        float4 v3 = __ldg(&z4[s3 * 32 + lane]);
        float x0 = v0.x - zd.x, y0 = v0.y - zd.y, u0 = v0.z - zd.z, w0 = v0.w - zd.w;
        float x1 = v1.x - zd.x, y1 = v1.y - zd.y, u1 = v1.z - zd.z, w1 = v1.w - zd.w;
        float x2 = v2.x - zd.x, y2 = v2.y - zd.y, u2 = v2.z - zd.z, w2 = v2.w - zd.w;
        float x3 = v3.x - zd.x, y3 = v3.y - zd.y, u3 = v3.z - zd.z, w3 = v3.w - zd.w;
        e0 += x0 * x0 + y0 * y0 + u0 * u0 + w0 * w0;
        e1 += x1 * x1 + y1 * y1 + u1 * u1 + w1 * w1;
        e2 += x2 * x2 + y2 * y2 + u2 * u2 + w2 * w2;
        e3 += x3 * x3 + y3 * y3 + u3 * u3 + w3 * w3;
    }
    for (; j < end; j++) {
        int s0 = g_csr[j];
        float4 v0 = __ldg(&z4[s0 * 32 + lane]);
        float x0 = v0.x - zd.x, y0 = v0.y - zd.y, u0 = v0.z - zd.z, w0 = v0.w - zd.w;
        e0 += x0 * x0 + y0 * y0 + u0 * u0 + w0 * w0;
    }
    float Et = warp_sum((e0 + e1) + (e2 + e3));
    if (lane == 0) {
        g_s.E[n] = Et;
        skey[wid] = f2key(-Et / temp[0]);
    }
    __syncthreads();
    if (threadIdx.x == 0) {
        unsigned mx = 0u;
#pragma unroll
        for (int k = 0; k < 8; k++) mx = max(mx, skey[k]);
        atomicMax(&g_s.umax, mx);
    }
}

// S = sum e^{u-m}, U = sum e^{u-m}*u
__global__ void k_sum(const float* __restrict__ temp) {
    __shared__ float sS[8], sU[8];
    int i = blockIdx.x * blockDim.x + threadIdx.x;
    int lane = threadIdx.x & 31, wid = threadIdx.x >> 5;
    float vS = 0.f, vU = 0.f;
    if (i < NN) {
        float u = -g_s.E[i] / temp[0];
        float ex = expf(u - key2f(g_s.umax));
        vS = ex;
        vU = ex * u;
    }
    vS = warp_sum(vS);
    vU = warp_sum(vU);
    if (lane == 0) { sS[wid] = vS; sU[wid] = vU; }
    __syncthreads();
    if (threadIdx.x == 0) {
        float aS = 0.f, aU = 0.f;
#pragma unroll
        for (int k = 0; k < 8; k++) { aS += sS[k]; aU += sU[k]; }
        atomicAdd(&g_s.S, aS);
        atomicAdd(&g_s.U, aU);
    }
}

// Gradient, warp per node (no queue): coef==0 -> warp exits immediately.
// For active d: out[s] += c*(z_s - z_d) per in-edge, out[d] -= c*sum.
__global__ void __launch_bounds__(256) k_grad(const float* __restrict__ temp,
                                              const float* __restrict__ weight,
                                              float* __restrict__ out) {
    int t = blockIdx.x * blockDim.x + threadIdx.x;
    int d = t >> 5, lane = t & 31;
    float T = temp[0];
    float c = coef_of(g_s.E[d], T, key2f(g_s.umax),
                      g_s.S, g_s.U, 2.0f * weight[0]);
    if (c == 0.0f) return;
    const float4* z4 = (const float4*)g_z;
    float4 zd = z4[d * 32 + lane];
    float4 sum = make_float4(0.f, 0.f, 0.f, 0.f);
    int beg = g_rowp[d], end = g_rowp[d + 1];
    for (int j = beg; j < end; j++) {
        int ss = g_csr[j];
        float4 zs = z4[ss * 32 + lane];
        float dx = zs.x - zd.x, dy = zs.y - zd.y;
        float dz = zs.z - zd.z, dw = zs.w - zd.w;
        red_add_v4(&out[ss * DD + lane * 4], c * dx, c * dy, c * dz, c * dw);
        sum.x += dx; sum.y += dy; sum.z += dz; sum.w += dw;
    }
    red_add_v4(&out[d * DD + lane * 4], -c * sum.x, -c * sum.y,
               -c * sum.z, -c * sum.w);
}

// ---------------- launch ----------------
extern "C" void kernel_launch(void* const* d_in, const int* in_sizes, int n_in,
                              void* d_out, int out_size) {
    const float* x      = (const float*)d_in[0];
    const void*  ei     = d_in[1];
    const float* weight = (const float*)d_in[2];
    const float* temp   = (const float*)d_in[3];
    const float* W      = (const float*)d_in[4];
    const float* b      = (const float*)d_in[5];
    float* out = (float*)d_out;

    // lazily-created side stream + fork/join events (host resources; no device mem)
    static cudaStream_t s_side = nullptr;
    static cudaEvent_t  ev_fork = nullptr, ev_join = nullptr;
    if (s_side == nullptr) {
        cudaStreamCreateWithFlags(&s_side, cudaStreamNonBlocking);
        cudaEventCreateWithFlags(&ev_fork, cudaEventDisableTiming);
        cudaEventCreateWithFlags(&ev_join, cudaEventDisableTiming);
    }

    void* scr = nullptr;
    cudaGetSymbolAddress(&scr, g_s);

    const int TB = 256;
    const int gE = (NE + TB - 1) / TB;        // 2500
    const int gW = (NN * 32) / TB;            // 6250 (warp per node, exact)
    const int gN = NB;                        // 196

    // fork: GEMM on side stream, CSR build on main stream, concurrently
    cudaEventRecord(ev_fork, 0);
    cudaStreamWaitEvent(s_side, ev_fork, 0);
    k_gemm<<<(NN + 63) / 64, TB, 0, s_side>>>(x, W);
    cudaEventRecord(ev_join, s_side);

    cudaMemsetAsync(scr, 0, sizeof(Scr));
    k_prep <<<gE, TB>>>(ei);
    k_scan1<<<gN, TB>>>();
    k_scan2<<<1,  TB>>>();
    k_scan3<<<gN, TB>>>();
    k_fill <<<gE, TB>>>(ei);

    cudaStreamWaitEvent(0, ev_join, 0);       // join: need g_h + CSR

    k_gatherz<<<gW, TB>>>(b, out);
    k_energy <<<gW, TB>>>(temp);
    k_sum    <<<gN, TB>>>(temp);
    k_grad   <<<gW, TB>>>(temp, weight, out);
}